// round 1
// baseline (speedup 1.0000x reference)
#include <cuda_runtime.h>
#include <math.h>

#define B_N 32
#define C_N 64
#define M_N 16384
#define CH_N 8
#define MC_N (M_N / CH_N)     /* 2048 m per chunk */
#define SUB_N 128             /* m per shared subtile */
#define NSUB_N (MC_N / SUB_N) /* 16 */

// Scratch (device globals: no allocation allowed)
__device__ float g_pgram[B_N * CH_N * C_N * C_N]; // partial grams (4 MB)
__device__ float g_prow[B_N * CH_N * C_N];        // partial row sums
__device__ float g_y[B_N * C_N];                  // gate values

// Swizzled layout for 64-float rows: 16B chunk index XORed with low 3 bits of (row>>2).
// Guarantees conflict-free (2-wavefront) LDS.128 when 16 threads read 16 different rows.
__device__ __forceinline__ int swz64(int r, int c) {
    return r * 64 + (((c >> 2) ^ ((r >> 2) & 7)) << 2) + (c & 3);
}

// ---------------------------------------------------------------------------
// Pass 1: xd = x - prev (staged into d_out), partial gram + row sums per chunk
// ---------------------------------------------------------------------------
__global__ __launch_bounds__(256) void cov_pass_kernel(
    const float* __restrict__ x, const float* __restrict__ prev,
    float* __restrict__ out)
{
    __shared__ float sm[C_N * SUB_N]; // 32 KB, swizzled in 16B chunks
    const int blk = blockIdx.x;       // b*CH + ch
    const int b = blk >> 3;
    const int ch = blk & 7;
    const int tid = threadIdx.x;
    const int tx = tid & 15, ty = tid >> 4;
    const int warp = tid >> 5, lane = tid & 31;
    const long base = (long)b * C_N * M_N + (long)ch * MC_N;

    float acc[4][4];
#pragma unroll
    for (int i = 0; i < 4; i++)
#pragma unroll
        for (int j = 0; j < 4; j++) acc[i][j] = 0.0f;
    float rowacc[8];
#pragma unroll
    for (int k = 0; k < 8; k++) rowacc[k] = 0.0f;

    float4* sm4 = reinterpret_cast<float4*>(sm);
    const int keyA = ty & 7, keyB = tx & 7;

    for (int s = 0; s < NSUB_N; s++) {
        __syncthreads();
        const int m0 = s * SUB_N;
        // Load 64x128 tile: each thread 8 float4, coalesced (warp = one row segment)
#pragma unroll
        for (int k = 0; k < 8; k++) {
            int f = tid + k * 256;
            int c = f >> 5;       // channel row (constant per warp per k)
            int m4i = f & 31;     // float4 within row
            long g = base + (long)c * M_N + m0;
            const float4 xv = reinterpret_cast<const float4*>(x + g)[m4i];
            const float4 pv = reinterpret_cast<const float4*>(prev + g)[m4i];
            float4 d;
            d.x = xv.x - pv.x; d.y = xv.y - pv.y;
            d.z = xv.z - pv.z; d.w = xv.w - pv.w;
            reinterpret_cast<float4*>(out + g)[m4i] = d; // stage xd
            rowacc[k] += (d.x + d.y) + (d.z + d.w);
            sm4[c * 32 + (m4i ^ ((c >> 2) & 7))] = d;    // swizzled store
        }
        __syncthreads();
        // Rank-128 update of 4x4 register tile, 4-m vectorized
#pragma unroll 4
        for (int m4i = 0; m4i < 32; m4i++) {
            float4 a0 = sm4[(4 * ty + 0) * 32 + (m4i ^ keyA)];
            float4 a1 = sm4[(4 * ty + 1) * 32 + (m4i ^ keyA)];
            float4 a2 = sm4[(4 * ty + 2) * 32 + (m4i ^ keyA)];
            float4 a3 = sm4[(4 * ty + 3) * 32 + (m4i ^ keyA)];
            float4 b0 = sm4[(4 * tx + 0) * 32 + (m4i ^ keyB)];
            float4 b1 = sm4[(4 * tx + 1) * 32 + (m4i ^ keyB)];
            float4 b2 = sm4[(4 * tx + 2) * 32 + (m4i ^ keyB)];
            float4 b3 = sm4[(4 * tx + 3) * 32 + (m4i ^ keyB)];
            float4 av[4] = {a0, a1, a2, a3};
            float4 bv[4] = {b0, b1, b2, b3};
#pragma unroll
            for (int i = 0; i < 4; i++)
#pragma unroll
                for (int j = 0; j < 4; j++) {
                    acc[i][j] = fmaf(av[i].x, bv[j].x, acc[i][j]);
                    acc[i][j] = fmaf(av[i].y, bv[j].y, acc[i][j]);
                    acc[i][j] = fmaf(av[i].z, bv[j].z, acc[i][j]);
                    acc[i][j] = fmaf(av[i].w, bv[j].w, acc[i][j]);
                }
        }
    }

    // Write partial gram (deterministic slot, no atomics/zeroing)
    float* pg = g_pgram + blk * 4096;
#pragma unroll
    for (int i = 0; i < 4; i++)
#pragma unroll
        for (int j = 0; j < 4; j++)
            pg[(4 * ty + i) * 64 + 4 * tx + j] = acc[i][j];

    // Row sums: all lanes of a warp share the same channel for each k
#pragma unroll
    for (int k = 0; k < 8; k++) {
        float v = rowacc[k];
#pragma unroll
        for (int o = 16; o; o >>= 1) v += __shfl_xor_sync(0xffffffffu, v, o);
        if (lane == 0) g_prow[blk * 64 + warp + 8 * k] = v;
    }
}

// ---------------------------------------------------------------------------
// 64x64 shared-memory matmul, B operand read row-wise (valid: all NS iterates
// are symmetric polynomials of An). MODE: 0 plain, 1 0.5*(3I-P), 2 3I-P, 3 scale*P
// ---------------------------------------------------------------------------
template <int MODE>
__device__ __forceinline__ void mm64(float* __restrict__ D,
    const float* __restrict__ A, const float* __restrict__ Bm,
    int tx, int ty, float scale)
{
    __syncthreads(); // inputs from previous step are complete
    const float4* A4 = reinterpret_cast<const float4*>(A);
    const float4* B4 = reinterpret_cast<const float4*>(Bm);
    const int keyA = ty & 7, keyB = tx & 7;
    float acc[4][4];
#pragma unroll
    for (int i = 0; i < 4; i++)
#pragma unroll
        for (int j = 0; j < 4; j++) acc[i][j] = 0.0f;
#pragma unroll
    for (int k4 = 0; k4 < 16; k4++) {
        float4 a[4], bb[4];
#pragma unroll
        for (int i = 0; i < 4; i++) a[i] = A4[(4 * ty + i) * 16 + (k4 ^ keyA)];
#pragma unroll
        for (int j = 0; j < 4; j++) bb[j] = B4[(4 * tx + j) * 16 + (k4 ^ keyB)];
#pragma unroll
        for (int i = 0; i < 4; i++)
#pragma unroll
            for (int j = 0; j < 4; j++) {
                acc[i][j] = fmaf(a[i].x, bb[j].x, acc[i][j]);
                acc[i][j] = fmaf(a[i].y, bb[j].y, acc[i][j]);
                acc[i][j] = fmaf(a[i].z, bb[j].z, acc[i][j]);
                acc[i][j] = fmaf(a[i].w, bb[j].w, acc[i][j]);
            }
    }
    __syncthreads(); // all reads done -> safe to overwrite aliased operand
    float4* D4 = reinterpret_cast<float4*>(D);
#pragma unroll
    for (int i = 0; i < 4; i++) {
        int r = 4 * ty + i;
        float fv[4];
#pragma unroll
        for (int j = 0; j < 4; j++) {
            int c = 4 * tx + j;
            float t = acc[i][j];
            if (MODE == 1) t = 0.5f * ((r == c ? 3.0f : 0.0f) - t);
            else if (MODE == 2) t = (r == c ? 3.0f : 0.0f) - t;
            else if (MODE == 3) t = t * scale;
            fv[j] = t;
        }
        D4[r * 16 + (tx ^ keyA)] = make_float4(fv[0], fv[1], fv[2], fv[3]);
    }
}

// ---------------------------------------------------------------------------
// Pass 2: reduce partials -> cov -> Newton-Schulz sqrtm -> column means -> MLP
// One CTA per batch. Dynamic shared: 4 matrices (16 KB each) + 128-float scratch.
// ---------------------------------------------------------------------------
__global__ __launch_bounds__(256) void ns_pass_kernel(
    const float* __restrict__ w1, const float* __restrict__ b1v,
    const float* __restrict__ w2, const float* __restrict__ b2v)
{
    extern __shared__ float sh[];
    float* An = sh;
    float* Ym = sh + 4096;
    float* Zm = sh + 8192;
    float* Tm = sh + 12288;
    float* scr = sh + 16384; // [0..63] rsum/s, [64] normA, [96..103] h
    const int b = blockIdx.x;
    const int tid = threadIdx.x;
    const int tx = tid & 15, ty = tid >> 4;

    if (tid < 64) {
        float r = 0.0f;
#pragma unroll
        for (int ch = 0; ch < CH_N; ch++) r += g_prow[(b * CH_N + ch) * 64 + tid];
        scr[tid] = r;
    }
    __syncthreads();
    const float invM = 1.0f / (float)M_N;
    for (int idx = tid; idx < 4096; idx += 256) {
        float g = 0.0f;
#pragma unroll
        for (int ch = 0; ch < CH_N; ch++) g += g_pgram[(b * CH_N + ch) * 4096 + idx];
        int i = idx >> 6, j = idx & 63;
        An[swz64(i, j)] = (g - scr[i] * scr[j] * invM) * invM;
    }
    __syncthreads();
    if (tid == 0) {
        float t = 0.0f;
        for (int i = 0; i < 64; i++) t += An[swz64(i, i)];
        scr[64] = t;
    }
    __syncthreads();
    const float normA = scr[64];
    const float invN = 1.0f / normA;
    for (int idx = tid; idx < 4096; idx += 256) An[idx] *= invN;
    __syncthreads();
    // T = ZY0 = 0.5*(3I - An)
    for (int idx = tid; idx < 4096; idx += 256) {
        int i = idx >> 6, j = idx & 63;
        int o = swz64(i, j);
        Tm[o] = 0.5f * ((i == j ? 3.0f : 0.0f) - An[o]);
    }
    mm64<0>(Ym, An, Tm, tx, ty, 1.0f);   // Y = An @ ZY
    for (int idx = tid; idx < 4096; idx += 256) Zm[idx] = Tm[idx]; // Z = ZY
#pragma unroll 1
    for (int it = 0; it < 3; it++) {
        mm64<1>(Tm, Zm, Ym, tx, ty, 1.0f); // ZY = 0.5*(3I - Z@Y)
        mm64<0>(Ym, Ym, Tm, tx, ty, 1.0f); // Y = Y @ ZY
        mm64<0>(Zm, Tm, Zm, tx, ty, 1.0f); // Z = ZY @ Z
    }
    mm64<2>(Tm, Zm, Ym, tx, ty, 1.0f);                    // T = 3I - Z@Y
    mm64<3>(An, Ym, Tm, tx, ty, 0.5f * sqrtf(normA));     // result into An

    __syncthreads();
    // s[c] = mean over rows of cov_sqrt
    if (tid < 64) {
        float sv = 0.0f;
        for (int r = 0; r < 64; r++) sv += An[swz64(r, tid)];
        scr[tid] = sv * (1.0f / 64.0f);
    }
    __syncthreads();
    if (tid < 8) {
        float h = b1v[tid];
        for (int c = 0; c < 64; c++) h = fmaf(w1[tid * 64 + c], scr[c], h);
        scr[96 + tid] = fmaxf(h, 0.0f);
    }
    __syncthreads();
    if (tid < 64) {
        float t = b2v[tid];
#pragma unroll
        for (int o = 0; o < 8; o++) t = fmaf(w2[tid * 8 + o], scr[96 + o], t);
        g_y[b * 64 + tid] = 1.0f / (1.0f + __expf(-t));
    }
}

// ---------------------------------------------------------------------------
// Pass 3: out[b,c,:] *= y[b,c]   (in-place on staged xd)
// ---------------------------------------------------------------------------
__global__ __launch_bounds__(256) void scale_kernel(float* __restrict__ out)
{
    const int idx = blockIdx.x * 256 + threadIdx.x;   // float4 index
    const float v = g_y[idx >> 12];                   // 4096 float4 per (b,c)
    float4* o4 = reinterpret_cast<float4*>(out);
    float4 d = o4[idx];
    d.x *= v; d.y *= v; d.z *= v; d.w *= v;
    o4[idx] = d;
}

extern "C" void kernel_launch(void* const* d_in, const int* in_sizes, int n_in,
                              void* d_out, int out_size)
{
    const float* prev = (const float*)d_in[0];
    const float* x    = (const float*)d_in[1];
    const float* w1   = (const float*)d_in[2];
    const float* b1   = (const float*)d_in[3];
    const float* w2   = (const float*)d_in[4];
    const float* b2   = (const float*)d_in[5];
    float* out = (float*)d_out;

    cudaFuncSetAttribute(ns_pass_kernel,
                         cudaFuncAttributeMaxDynamicSharedMemorySize, 16512 * 4);

    cov_pass_kernel<<<B_N * CH_N, 256>>>(x, prev, out);
    ns_pass_kernel<<<B_N, 256, 16512 * 4>>>(w1, b1, w2, b2);
    scale_kernel<<<(B_N * C_N * M_N) / 1024, 256>>>(out);
}